// round 16
// baseline (speedup 1.0000x reference)
#include <cuda_runtime.h>
#include <cuda_fp16.h>
#include <cstdint>

#define DI __device__ __forceinline__

// ---------------- constants ----------------
constexpr int DIM = 128;
constexpr int ROW_FLOATS = DIM * DIM;        // 16384 floats per sample
constexpr int ROW_BYTES = DIM * 2;           // 256 B per fp16 tile row
constexpr int TILE_BYTES = DIM * ROW_BYTES;  // 32 KB
constexpr int NT = 256;                      // 8 warps; 1 CTA per SM
constexpr int CHUNKS_PT = 2048 / NT;         // 8 16B-chunks per thread per tile

// SMEM map: 3 fp16 tiles + bias fragments = 160 KB (1 CTA/SM)
constexpr int OFF_WB = 0;
constexpr int OFF_WA = 1 * TILE_BYTES;
constexpr int OFF_U  = 2 * TILE_BYTES;       // X -> T -> next X (aliased)
constexpr int OFF_BF = 3 * TILE_BYTES;       // bias fragments: 8 warps x 8 KB
constexpr int SMEM_BYTES = OFF_BF + 8 * 8192;  // 163840 B

// ---------------- helpers ----------------
DI uint32_t smem_u32(const void* p) {
    uint32_t a;
    asm("{ .reg .u64 t; cvta.to.shared.u64 t, %1; cvt.u32.u64 %0, t; }" : "=r"(a) : "l"(p));
    return a;
}

// Byte offset of (row, col[fp16]) in a swizzled 128x128 fp16 tile.
// Row = 256 B = 16 chunks of 16 B; chunk index XORed with (row & 7) so
// 8 consecutive rows hit 8 distinct bank groups (conflict-free ldmatrix).
DI uint32_t toff(int row, int col) {
    return (uint32_t)(row * ROW_BYTES) + ((((col >> 3) ^ (row & 7)) << 4)) +
           ((col & 7) << 1);
}

DI void ldsm4(uint32_t& r0, uint32_t& r1, uint32_t& r2, uint32_t& r3, uint32_t a) {
    asm volatile("ldmatrix.sync.aligned.m8n8.x4.shared.b16 {%0,%1,%2,%3}, [%4];"
                 : "=r"(r0), "=r"(r1), "=r"(r2), "=r"(r3) : "r"(a));
}

DI void mma16816(float* d, const uint32_t* a, uint32_t b0, uint32_t b1) {
    asm volatile(
        "mma.sync.aligned.m16n8k16.row.col.f32.f16.f16.f32 "
        "{%0,%1,%2,%3}, {%4,%5,%6,%7}, {%8,%9}, {%0,%1,%2,%3};"
        : "+f"(d[0]), "+f"(d[1]), "+f"(d[2]), "+f"(d[3])
        : "r"(a[0]), "r"(a[1]), "r"(a[2]), "r"(a[3]), "r"(b0), "r"(b1));
}

DI uint32_t f2h2(float a, float b) {
    __half2 h = __floats2half2_rn(a, b);
    return *reinterpret_cast<uint32_t*>(&h);
}

// Load one 16B fp16 chunk's worth of fp32 (32 B) and convert.
DI uint4 load_cvt_chunk(const float* __restrict__ src, int g) {
    const float4* p =
        reinterpret_cast<const float4*>(src + (g >> 4) * DIM + ((g & 15) << 3));
    float4 v0 = p[0];
    float4 v1 = p[1];
    uint4 h;
    h.x = f2h2(v0.x, v0.y);
    h.y = f2h2(v0.z, v0.w);
    h.z = f2h2(v1.x, v1.y);
    h.w = f2h2(v1.z, v1.w);
    return h;
}

// Load 128x128 fp32 from gmem, convert to single fp16 swizzled tile.
DI void cvt_x(const float* __restrict__ src, char* smem, int off, int tid) {
#pragma unroll
    for (int it = 0; it < CHUNKS_PT; it++) {
        int g = tid + it * NT;
        *reinterpret_cast<uint4*>(smem + off + toff(g >> 4, (g & 15) << 3)) =
            load_cvt_chunk(src, g);
    }
}

// 128x128x128 fp16 GEMM, warp tile m32 x n64 (8 warps, grid 4x2).
DI void gemm1p(float acc[2][8][4], uint32_t a_t, uint32_t b_t,
               int m0, int n0, int lane) {
    const int a_row = lane & 15;
    const int a_col = (lane >> 4) << 3;
    const int b_row = (lane & 7) + ((lane >> 4) << 3);
    const int b_col = ((lane >> 3) & 1) << 3;

#pragma unroll
    for (int k = 0; k < 8; k++) {
        const int kb = k << 4;
        uint32_t A[2][4];
#pragma unroll
        for (int mt = 0; mt < 2; mt++) {
            uint32_t o = toff(m0 + mt * 16 + a_row, kb + a_col);
            ldsm4(A[mt][0], A[mt][1], A[mt][2], A[mt][3], a_t + o);
        }
#pragma unroll
        for (int p = 0; p < 4; p++) {
            uint32_t B[4];
            uint32_t o = toff(n0 + p * 16 + b_row, kb + b_col);
            ldsm4(B[0], B[1], B[2], B[3], b_t + o);
#pragma unroll
            for (int mt = 0; mt < 2; mt++) {
#pragma unroll
                for (int qn = 0; qn < 2; qn++) {
                    mma16816(acc[mt][p * 2 + qn], A[mt], B[qn * 2], B[qn * 2 + 1]);
                }
            }
        }
    }
}

DI void zero_acc(float acc[2][8][4]) {
#pragma unroll
    for (int mt = 0; mt < 2; mt++)
#pragma unroll
        for (int nt = 0; nt < 8; nt++)
#pragma unroll
            for (int i = 0; i < 4; i++) acc[mt][nt][i] = 0.f;
}

// ---------------- kernel ----------------
// GEMM1: D1[o_b, j] = sum_k Wb[o_b,k] * X[j,k]   (B = X natural row-major)
// GEMM2: D2[o_a, o_b] = sum_j Wa[o_a,j] * T[o_b,j]
// out[n, o_a*128+o_b] = D2 + bias  (bias fragments preloaded in smem)
__global__ void __launch_bounds__(NT, 1)
krone_kernel(const float* __restrict__ x, const float* __restrict__ wa,
             const float* __restrict__ wb, const float* __restrict__ bias,
             float* __restrict__ out, int n_samples) {
    extern __shared__ char smem[];
    const uint32_t sb = smem_u32(smem);
    const int tid = threadIdx.x;
    const int wid = tid >> 5;
    const int lane = tid & 31;
    const int m0 = (wid & 3) * 32;     // output rows
    const int n0 = (wid >> 2) * 64;    // output cols

    const int er = lane >> 2;
    const int ec = (lane & 3) << 1;

    // One-time: weights (fp16) + first sample -> smem
    cvt_x(wb, smem, OFF_WB, tid);
    cvt_x(wa, smem, OFF_WA, tid);
    {
        int n0s = blockIdx.x < n_samples ? blockIdx.x : 0;
        cvt_x(x + (size_t)n0s * ROW_FLOATS, smem, OFF_U, tid);
    }
    // One-time: bias fragments in lane-linear order.
    // Tile t = (mt*8 + nt)*2 + half; value = bias[row*128 + col .. +1].
    {
        float2* bf = reinterpret_cast<float2*>(smem + OFF_BF + wid * 8192);
#pragma unroll
        for (int mt = 0; mt < 2; mt++) {
#pragma unroll
            for (int nt = 0; nt < 8; nt++) {
#pragma unroll
                for (int h = 0; h < 2; h++) {
                    const int row = m0 + mt * 16 + h * 8 + er;
                    const int col = n0 + nt * 8 + ec;
                    const int t = (mt * 8 + nt) * 2 + h;
                    bf[t * 32 + lane] =
                        *reinterpret_cast<const float2*>(bias + row * DIM + col);
                }
            }
        }
    }
    __syncthreads();

    const float2* bf = reinterpret_cast<const float2*>(smem + OFF_BF + wid * 8192);

    float acc[2][8][4];
    uint4 pfh[CHUNKS_PT];              // next sample, fp16-converted (32 regs)

    for (int n = blockIdx.x; n < n_samples; n += gridDim.x) {
        // ===== GEMM1: reads U (X), Wb =====
        zero_acc(acc);
        gemm1p(acc, sb + OFF_WB, sb + OFF_U, m0, n0, lane);
        __syncthreads();   // all warps done reading U

        // ===== prefetch + convert next sample's x (full tile) =====
        int np = n + gridDim.x;
        if (np >= n_samples) np = n;   // clamp: harmless reload on last iter
        const float* src = x + (size_t)np * ROW_FLOATS;
#pragma unroll
        for (int it = 0; it < CHUNKS_PT; it++)
            pfh[it] = load_cvt_chunk(src, tid + it * NT);

        // ===== storeT: T[o_b][j] overwrites U =====
#pragma unroll
        for (int mt = 0; mt < 2; mt++) {
#pragma unroll
            for (int nt = 0; nt < 8; nt++) {
                const int col = n0 + nt * 8 + ec;
                *reinterpret_cast<uint32_t*>(
                    smem + OFF_U + toff(m0 + mt * 16 + er, col)) =
                    f2h2(acc[mt][nt][0], acc[mt][nt][1]);
                *reinterpret_cast<uint32_t*>(
                    smem + OFF_U + toff(m0 + mt * 16 + er + 8, col)) =
                    f2h2(acc[mt][nt][2], acc[mt][nt][3]);
            }
        }
        __syncthreads();   // T ready

        // ===== GEMM2: acc init = bias fragments (conflict-free LDS) =====
#pragma unroll
        for (int mt = 0; mt < 2; mt++) {
#pragma unroll
            for (int nt = 0; nt < 8; nt++) {
                const int t = (mt * 8 + nt) * 2;
                float2 b0 = bf[t * 32 + lane];
                float2 b1 = bf[(t + 1) * 32 + lane];
                acc[mt][nt][0] = b0.x;
                acc[mt][nt][1] = b0.y;
                acc[mt][nt][2] = b1.x;
                acc[mt][nt][3] = b1.y;
            }
        }
        gemm1p(acc, sb + OFF_WA, sb + OFF_U, m0, n0, lane);

        // ===== epilogue: pure STG =====
        float* outn = out + (size_t)n * ROW_FLOATS;
#pragma unroll
        for (int mt = 0; mt < 2; mt++) {
#pragma unroll
            for (int nt = 0; nt < 8; nt++) {
                const int col = n0 + nt * 8 + ec;
                const int row = m0 + mt * 16 + er;
                *reinterpret_cast<float2*>(outn + row * DIM + col) =
                    make_float2(acc[mt][nt][0], acc[mt][nt][1]);
                *reinterpret_cast<float2*>(outn + (row + 8) * DIM + col) =
                    make_float2(acc[mt][nt][2], acc[mt][nt][3]);
            }
        }
        __syncthreads();   // all warps done reading U (T)

        // ===== stage prefetched next X into U (pure STS, full tile) =====
#pragma unroll
        for (int it = 0; it < CHUNKS_PT; it++) {
            int g = tid + it * NT;
            *reinterpret_cast<uint4*>(smem + OFF_U + toff(g >> 4, (g & 15) << 3)) =
                pfh[it];
        }
        __syncthreads();   // next X ready
    }
}

// ---------------- launcher ----------------
extern "C" void kernel_launch(void* const* d_in, const int* in_sizes, int n_in,
                              void* d_out, int out_size) {
    const float* x    = (const float*)d_in[0];
    const float* wa   = (const float*)d_in[1];
    const float* wb   = (const float*)d_in[2];
    const float* bias = (const float*)d_in[3];
    float* out = (float*)d_out;
    int n_samples = in_sizes[0] / ROW_FLOATS;

    cudaFuncSetAttribute(krone_kernel, cudaFuncAttributeMaxDynamicSharedMemorySize,
                         SMEM_BYTES);
    int grid = n_samples < 148 ? n_samples : 148;
    krone_kernel<<<grid, NT, SMEM_BYTES>>>(x, wa, wb, bias, out, n_samples);
}

// round 17
// speedup vs baseline: 1.5163x; 1.5163x over previous
#include <cuda_runtime.h>
#include <cuda_fp16.h>
#include <cstdint>

#define DI __device__ __forceinline__

// ---------------- constants ----------------
constexpr int DIM = 128;
constexpr int ROW_FLOATS = DIM * DIM;        // 16384 floats per sample
constexpr int ROW_BYTES = DIM * 2;           // 256 B per fp16 tile row
constexpr int TILE_BYTES = DIM * ROW_BYTES;  // 32 KB
constexpr int NT = 256;                      // 8 warps; 2 CTAs per SM
constexpr int CHUNKS_PT = 2048 / NT;         // 8 16B-chunks per thread per tile

// SMEM map: 3 tiles = 96 KB per CTA (2 CTAs/SM)
constexpr int OFF_WB = 0;
constexpr int OFF_WA = 1 * TILE_BYTES;
constexpr int OFF_U  = 2 * TILE_BYTES;       // X -> T -> next X (aliased)
constexpr int SMEM_BYTES = 3 * TILE_BYTES;   // 98304 B

// Fragment-linear bias: warp w, tile t (0..31), lane l -> [w*2048 + t*64 + 2l]
__device__ float g_bias_frag[8 * 2048];      // 64 KB scratch (L2-resident)

// ---------------- helpers ----------------
DI uint32_t smem_u32(const void* p) {
    uint32_t a;
    asm("{ .reg .u64 t; cvta.to.shared.u64 t, %1; cvt.u32.u64 %0, t; }" : "=r"(a) : "l"(p));
    return a;
}

// Byte offset of (row, col[fp16]) in a swizzled 128x128 fp16 tile.
// Row = 256 B = 16 chunks of 16 B; chunk index XORed with (row & 7) so
// 8 consecutive rows hit 8 distinct bank groups (conflict-free ldmatrix).
DI uint32_t toff(int row, int col) {
    return (uint32_t)(row * ROW_BYTES) + ((((col >> 3) ^ (row & 7)) << 4)) +
           ((col & 7) << 1);
}

DI void ldsm4(uint32_t& r0, uint32_t& r1, uint32_t& r2, uint32_t& r3, uint32_t a) {
    asm volatile("ldmatrix.sync.aligned.m8n8.x4.shared.b16 {%0,%1,%2,%3}, [%4];"
                 : "=r"(r0), "=r"(r1), "=r"(r2), "=r"(r3) : "r"(a));
}

DI void mma16816(float* d, const uint32_t* a, uint32_t b0, uint32_t b1) {
    asm volatile(
        "mma.sync.aligned.m16n8k16.row.col.f32.f16.f16.f32 "
        "{%0,%1,%2,%3}, {%4,%5,%6,%7}, {%8,%9}, {%0,%1,%2,%3};"
        : "+f"(d[0]), "+f"(d[1]), "+f"(d[2]), "+f"(d[3])
        : "r"(a[0]), "r"(a[1]), "r"(a[2]), "r"(a[3]), "r"(b0), "r"(b1));
}

DI uint32_t f2h2(float a, float b) {
    __half2 h = __floats2half2_rn(a, b);
    return *reinterpret_cast<uint32_t*>(&h);
}

// Load one 16B fp16 chunk's worth of fp32 (32 B) and convert.
DI uint4 load_cvt_chunk(const float* __restrict__ src, int g) {
    const float4* p =
        reinterpret_cast<const float4*>(src + (g >> 4) * DIM + ((g & 15) << 3));
    float4 v0 = p[0];
    float4 v1 = p[1];
    uint4 h;
    h.x = f2h2(v0.x, v0.y);
    h.y = f2h2(v0.z, v0.w);
    h.z = f2h2(v1.x, v1.y);
    h.w = f2h2(v1.z, v1.w);
    return h;
}

// Load 128x128 fp32 from gmem, convert to single fp16 swizzled tile.
DI void cvt_x(const float* __restrict__ src, char* smem, int off, int tid) {
#pragma unroll
    for (int it = 0; it < CHUNKS_PT; it++) {
        int g = tid + it * NT;
        *reinterpret_cast<uint4*>(smem + off + toff(g >> 4, (g & 15) << 3)) =
            load_cvt_chunk(src, g);
    }
}

// 128x128x128 fp16 GEMM, warp tile m32 x n64 (8 warps, grid 4x2).
DI void gemm1p(float acc[2][8][4], uint32_t a_t, uint32_t b_t,
               int m0, int n0, int lane) {
    const int a_row = lane & 15;
    const int a_col = (lane >> 4) << 3;
    const int b_row = (lane & 7) + ((lane >> 4) << 3);
    const int b_col = ((lane >> 3) & 1) << 3;

#pragma unroll
    for (int k = 0; k < 8; k++) {
        const int kb = k << 4;
        uint32_t A[2][4];
#pragma unroll
        for (int mt = 0; mt < 2; mt++) {
            uint32_t o = toff(m0 + mt * 16 + a_row, kb + a_col);
            ldsm4(A[mt][0], A[mt][1], A[mt][2], A[mt][3], a_t + o);
        }
#pragma unroll
        for (int p = 0; p < 4; p++) {
            uint32_t B[4];
            uint32_t o = toff(n0 + p * 16 + b_row, kb + b_col);
            ldsm4(B[0], B[1], B[2], B[3], b_t + o);
#pragma unroll
            for (int mt = 0; mt < 2; mt++) {
#pragma unroll
                for (int qn = 0; qn < 2; qn++) {
                    mma16816(acc[mt][p * 2 + qn], A[mt], B[qn * 2], B[qn * 2 + 1]);
                }
            }
        }
    }
}

DI void zero_acc(float acc[2][8][4]) {
#pragma unroll
    for (int mt = 0; mt < 2; mt++)
#pragma unroll
        for (int nt = 0; nt < 8; nt++)
#pragma unroll
            for (int i = 0; i < 4; i++) acc[mt][nt][i] = 0.f;
}

// ---------------- prep kernel: bias -> fragment-linear order ----------------
__global__ void bias_prep_kernel(const float* __restrict__ bias) {
    const int tid = threadIdx.x;
    const int wid = tid >> 5;
    const int lane = tid & 31;
    const int m0 = (wid & 3) * 32;
    const int n0 = (wid >> 2) * 64;
    const int er = lane >> 2;
    const int ec = (lane & 3) << 1;
#pragma unroll
    for (int mt = 0; mt < 2; mt++) {
#pragma unroll
        for (int nt = 0; nt < 8; nt++) {
#pragma unroll
            for (int h = 0; h < 2; h++) {
                const int row = m0 + mt * 16 + h * 8 + er;
                const int col = n0 + nt * 8 + ec;
                const int t = (mt * 8 + nt) * 2 + h;
                const float2 v =
                    *reinterpret_cast<const float2*>(bias + row * DIM + col);
                g_bias_frag[wid * 2048 + t * 64 + lane * 2]     = v.x;
                g_bias_frag[wid * 2048 + t * 64 + lane * 2 + 1] = v.y;
            }
        }
    }
}

// ---------------- main kernel ----------------
// GEMM1: D1[o_b, j] = sum_k Wb[o_b,k] * X[j,k]   (B = X natural row-major)
// GEMM2: D2[o_a, o_b] = sum_j Wa[o_a,j] * T[o_b,j]
// out[n, o_a*128+o_b] = D2 + bias  (bias from fragment-linear scratch)
__global__ void __launch_bounds__(NT, 2)
krone_kernel(const float* __restrict__ x, const float* __restrict__ wa,
             const float* __restrict__ wb, float* __restrict__ out,
             int n_samples) {
    extern __shared__ char smem[];
    const uint32_t sb = smem_u32(smem);
    const int tid = threadIdx.x;
    const int wid = tid >> 5;
    const int lane = tid & 31;
    const int m0 = (wid & 3) * 32;     // output rows
    const int n0 = (wid >> 2) * 64;    // output cols

    // One-time: weights (fp16) + first sample -> smem
    cvt_x(wb, smem, OFF_WB, tid);
    cvt_x(wa, smem, OFF_WA, tid);
    {
        int n0s = blockIdx.x < n_samples ? blockIdx.x : 0;
        cvt_x(x + (size_t)n0s * ROW_FLOATS, smem, OFF_U, tid);
    }
    __syncthreads();

    const int er = lane >> 2;
    const int ec = (lane & 3) << 1;
    const float* bfr = g_bias_frag + wid * 2048 + lane * 2;

    float acc[2][8][4];
    uint4 pfh[CHUNKS_PT];              // next sample, fp16-converted (32 regs)

    for (int n = blockIdx.x; n < n_samples; n += gridDim.x) {
        // ===== GEMM1: reads U (X), Wb =====
        zero_acc(acc);
        gemm1p(acc, sb + OFF_WB, sb + OFF_U, m0, n0, lane);
        __syncthreads();   // all warps done reading U

        // ===== prefetch + convert next sample's x (full tile) =====
        int np = n + gridDim.x;
        if (np >= n_samples) np = n;   // clamp: harmless reload on last iter
        const float* src = x + (size_t)np * ROW_FLOATS;
#pragma unroll
        for (int it = 0; it < CHUNKS_PT; it++)
            pfh[it] = load_cvt_chunk(src, tid + it * NT);

        // ===== storeT: T[o_b][j] overwrites U =====
#pragma unroll
        for (int mt = 0; mt < 2; mt++) {
#pragma unroll
            for (int nt = 0; nt < 8; nt++) {
                const int col = n0 + nt * 8 + ec;
                *reinterpret_cast<uint32_t*>(
                    smem + OFF_U + toff(m0 + mt * 16 + er, col)) =
                    f2h2(acc[mt][nt][0], acc[mt][nt][1]);
                *reinterpret_cast<uint32_t*>(
                    smem + OFF_U + toff(m0 + mt * 16 + er + 8, col)) =
                    f2h2(acc[mt][nt][2], acc[mt][nt][3]);
            }
        }
        __syncthreads();   // T ready

        // ===== GEMM2: acc init = bias fragments (coalesced LDG.64) =====
#pragma unroll
        for (int mt = 0; mt < 2; mt++) {
#pragma unroll
            for (int nt = 0; nt < 8; nt++) {
                const int t = (mt * 8 + nt) * 2;
                float2 b0 = *reinterpret_cast<const float2*>(bfr + t * 64);
                float2 b1 = *reinterpret_cast<const float2*>(bfr + (t + 1) * 64);
                acc[mt][nt][0] = b0.x;
                acc[mt][nt][1] = b0.y;
                acc[mt][nt][2] = b1.x;
                acc[mt][nt][3] = b1.y;
            }
        }
        gemm1p(acc, sb + OFF_WA, sb + OFF_U, m0, n0, lane);

        // ===== epilogue: pure STG =====
        float* outn = out + (size_t)n * ROW_FLOATS;
#pragma unroll
        for (int mt = 0; mt < 2; mt++) {
#pragma unroll
            for (int nt = 0; nt < 8; nt++) {
                const int col = n0 + nt * 8 + ec;
                const int row = m0 + mt * 16 + er;
                *reinterpret_cast<float2*>(outn + row * DIM + col) =
                    make_float2(acc[mt][nt][0], acc[mt][nt][1]);
                *reinterpret_cast<float2*>(outn + (row + 8) * DIM + col) =
                    make_float2(acc[mt][nt][2], acc[mt][nt][3]);
            }
        }
        __syncthreads();   // all warps done reading U (T)

        // ===== stage prefetched next X into U (pure STS, full tile) =====
#pragma unroll
        for (int it = 0; it < CHUNKS_PT; it++) {
            int g = tid + it * NT;
            *reinterpret_cast<uint4*>(smem + OFF_U + toff(g >> 4, (g & 15) << 3)) =
                pfh[it];
        }
        __syncthreads();   // next X ready
    }
}

// ---------------- launcher ----------------
extern "C" void kernel_launch(void* const* d_in, const int* in_sizes, int n_in,
                              void* d_out, int out_size) {
    const float* x    = (const float*)d_in[0];
    const float* wa   = (const float*)d_in[1];
    const float* wb   = (const float*)d_in[2];
    const float* bias = (const float*)d_in[3];
    float* out = (float*)d_out;
    int n_samples = in_sizes[0] / ROW_FLOATS;

    bias_prep_kernel<<<1, 256>>>(bias);

    cudaFuncSetAttribute(krone_kernel, cudaFuncAttributeMaxDynamicSharedMemorySize,
                         SMEM_BYTES);
    int grid = n_samples < 296 ? n_samples : 296;
    krone_kernel<<<grid, NT, SMEM_BYTES>>>(x, wa, wb, out, n_samples);
}